// round 4
// baseline (speedup 1.0000x reference)
#include <cuda_runtime.h>
#include <math.h>

#define NN 50000
#define NE 500000
#define HID 256
#define NLAYERS 15
#define EPSV 1e-5f
#define NROWB ((NN + 127) / 128)   // 391 row blocks over nodes

// ---------------- device scratch (no allocations allowed) ----------------
__device__ float g_h  [(size_t)NN * HID];
__device__ float g_agg[(size_t)NN * HID];
__device__ float g_out[(size_t)NN * HID];
__device__ float g_z1 [(size_t)NE * HID];
__device__ float g_z2 [(size_t)NE * HID];
__device__ int   g_rowptr[NN + 1];
__device__ int   g_woff[NN];
__device__ int   g_hist[NN];
__device__ int   g_colidx[NE];
__device__ float g_psum[NROWB * HID];
__device__ float g_psq [NROWB * HID];
__device__ float g_scale[HID];
__device__ float g_shift[HID];

// ---------------- CSR build (deterministic) ----------------
__global__ void k_zero_hist() {
    int i = blockIdx.x * blockDim.x + threadIdx.x;
    if (i < NN) g_hist[i] = 0;
}

__global__ void k_hist(const int* __restrict__ dst) {
    int e = blockIdx.x * blockDim.x + threadIdx.x;
    if (e < NE) atomicAdd(&g_hist[dst[e]], 1);
}

// single-block exclusive scan of g_hist -> g_rowptr (+ working copy g_woff)
__global__ void k_scan() {
    __shared__ int ss[1024];
    int t = threadIdx.x;
    int s0 = t * 49;
    int s1 = s0 + 49;
    if (s0 > NN) s0 = NN;
    if (s1 > NN) s1 = NN;
    int s = 0;
    for (int i = s0; i < s1; i++) s += g_hist[i];
    ss[t] = s;
    __syncthreads();
    for (int off = 1; off < 1024; off <<= 1) {
        int v = (t >= off) ? ss[t - off] : 0;
        __syncthreads();
        ss[t] += v;
        __syncthreads();
    }
    int run = (t > 0) ? ss[t - 1] : 0;
    for (int i = s0; i < s1; i++) {
        g_rowptr[i] = run;
        g_woff[i]   = run;
        run += g_hist[i];
    }
    if (t == 1023) g_rowptr[NN] = ss[1023];
}

__global__ void k_scatter(const int* __restrict__ dst) {
    int e = blockIdx.x * blockDim.x + threadIdx.x;
    if (e < NE) {
        int p = atomicAdd(&g_woff[dst[e]], 1);
        g_colidx[p] = e;   // store edge id (sorted per-bucket below -> deterministic)
    }
}

// sort each dst-bucket by edge id (order within bucket from atomics is
// nondeterministic; sorting restores a unique, replay-stable CSR), then
// replace edge ids with src node ids.
__global__ void k_sortbuckets(const int* __restrict__ src) {
    int n = blockIdx.x * blockDim.x + threadIdx.x;
    if (n >= NN) return;
    int s = g_rowptr[n], t = g_rowptr[n + 1];
    for (int i = s + 1; i < t; i++) {
        int v = g_colidx[i];
        int j = i - 1;
        while (j >= s && g_colidx[j] > v) { g_colidx[j + 1] = g_colidx[j]; j--; }
        g_colidx[j + 1] = v;
    }
    for (int i = s; i < t; i++) g_colidx[i] = src[g_colidx[i]];
}

// ---------------- input FC: h = x @ W_in.T  (IN_CH = 2) ----------------
__global__ void k_infc(const float* __restrict__ x, const float* __restrict__ Win) {
    __shared__ float w0[HID], w1[HID];
    int j = threadIdx.x;
    w0[j] = Win[2 * j];
    w1[j] = Win[2 * j + 1];
    __syncthreads();
    for (int i = blockIdx.x; i < NN; i += gridDim.x) {
        float a = x[2 * i], b = x[2 * i + 1];
        g_h[(size_t)i * HID + j] = a * w0[j] + b * w1[j];
    }
}

// ---------------- SpMM: agg[n] = sum over in-edges of h[src] ----------------
__global__ void k_spmm() {
    int warp = threadIdx.x >> 5, lane = threadIdx.x & 31;
    int n = blockIdx.x * 8 + warp;
    if (n >= NN) return;
    int s = g_rowptr[n], e = g_rowptr[n + 1];
    float4 a0 = make_float4(0.f, 0.f, 0.f, 0.f);
    float4 a1 = make_float4(0.f, 0.f, 0.f, 0.f);
    for (int i = s; i < e; i++) {
        int sr = g_colidx[i];
        const float4* p = (const float4*)(g_h + (size_t)sr * HID);
        float4 v0 = p[lane];
        float4 v1 = p[lane + 32];
        a0.x += v0.x; a0.y += v0.y; a0.z += v0.z; a0.w += v0.w;
        a1.x += v1.x; a1.y += v1.y; a1.z += v1.z; a1.w += v1.w;
    }
    float4* q = (float4*)(g_agg + (size_t)n * HID);
    q[lane]      = a0;
    q[lane + 32] = a1;
}

// ---------------- tiled fp32 GEMM, 128x128x8, 256 threads, 8x8 microtile ----
// MODE 0: C=g_out, A = [g_agg | g_h]  (K=512), B = [B0(Wrel) | B1(Wroot)], bias
// MODE 1: C=g_z1,  A = [h[src[e]] | h[dst[e]]] gathered (K=512), B = W1 [256x512]
// MODE 2: C=g_z2,  A = g_z1 (K=256), B = W2 [256x256]
template <int KTOT, int MODE, bool RELU>
__global__ void __launch_bounds__(256, 2) k_gemm(
    const float* __restrict__ B0, const float* __restrict__ B1,
    const float* __restrict__ bias,
    const int* __restrict__ esrc, const int* __restrict__ edst)
{
    constexpr int M = (MODE == 0) ? NN : NE;
    __shared__ float As[8][128];
    __shared__ float Bs[8][128];
    __shared__ int s_src[128];
    __shared__ int s_dst[128];

    const int tid = threadIdx.x;
    const int m0 = blockIdx.y * 128, n0 = blockIdx.x * 128;

    if (MODE == 1) {
        if (tid < 128) {
            int m = m0 + tid;
            s_src[tid] = (m < M) ? esrc[m] : 0;
        } else {
            int m = m0 + tid - 128;
            s_dst[tid - 128] = (m < M) ? edst[m] : 0;
        }
        __syncthreads();
    }

    const int tx = tid & 15, ty = tid >> 4;
    float acc[8][8];
#pragma unroll
    for (int i = 0; i < 8; i++)
#pragma unroll
        for (int j = 0; j < 8; j++) acc[i][j] = 0.f;

    const int arow = tid >> 1;
    const int a4 = (tid & 1) << 2;

    for (int k0 = 0; k0 < KTOT; k0 += 8) {
        float4 av = make_float4(0.f, 0.f, 0.f, 0.f);
        {
            int m = m0 + arow;
            int ka = k0 + a4;
            if (m < M) {
                const float* ap;
                if (MODE == 0) {
                    ap = ((ka < 256) ? g_agg : g_h) + (size_t)m * HID + (ka & 255);
                } else if (MODE == 1) {
                    int r = (ka < 256) ? s_src[arow] : s_dst[arow];
                    ap = g_h + (size_t)r * HID + (ka & 255);
                } else {
                    ap = g_z1 + (size_t)m * HID + ka;
                }
                av = *(const float4*)ap;
            }
        }
        float4 bv;
        {
            int nn = n0 + arow;
            int kb = k0 + a4;
            const float* bp;
            if (MODE == 0)      bp = ((kb < 256) ? B0 : B1) + nn * 256 + (kb & 255);
            else if (MODE == 1) bp = B0 + nn * 512 + kb;
            else                bp = B0 + nn * 256 + kb;
            bv = *(const float4*)bp;
        }
        __syncthreads();
        As[a4 + 0][arow] = av.x; As[a4 + 1][arow] = av.y;
        As[a4 + 2][arow] = av.z; As[a4 + 3][arow] = av.w;
        Bs[a4 + 0][arow] = bv.x; Bs[a4 + 1][arow] = bv.y;
        Bs[a4 + 2][arow] = bv.z; Bs[a4 + 3][arow] = bv.w;
        __syncthreads();
#pragma unroll
        for (int kk = 0; kk < 8; kk++) {
            float4 aa0 = *(const float4*)&As[kk][ty * 8];
            float4 aa1 = *(const float4*)&As[kk][ty * 8 + 4];
            float4 bb0 = *(const float4*)&Bs[kk][tx * 8];
            float4 bb1 = *(const float4*)&Bs[kk][tx * 8 + 4];
            float a[8] = {aa0.x, aa0.y, aa0.z, aa0.w, aa1.x, aa1.y, aa1.z, aa1.w};
            float b[8] = {bb0.x, bb0.y, bb0.z, bb0.w, bb1.x, bb1.y, bb1.z, bb1.w};
#pragma unroll
            for (int i = 0; i < 8; i++)
#pragma unroll
                for (int j = 0; j < 8; j++) acc[i][j] += a[i] * b[j];
        }
    }

    float* crow;
    if (MODE == 0) crow = g_out;
    else if (MODE == 1) crow = g_z1;
    else crow = g_z2;

#pragma unroll
    for (int i = 0; i < 8; i++) {
        int m = m0 + ty * 8 + i;
        if (m < M) {
#pragma unroll
            for (int j = 0; j < 8; j += 4) {
                int n = n0 + tx * 8 + j;
                float4 v;
                v.x = acc[i][j + 0] + bias[n + 0];
                v.y = acc[i][j + 1] + bias[n + 1];
                v.z = acc[i][j + 2] + bias[n + 2];
                v.w = acc[i][j + 3] + bias[n + 3];
                if (RELU) {
                    v.x = fmaxf(v.x, 0.f); v.y = fmaxf(v.y, 0.f);
                    v.z = fmaxf(v.z, 0.f); v.w = fmaxf(v.w, 0.f);
                }
                *(float4*)(crow + (size_t)m * HID + n) = v;
            }
        }
    }
}

// ---------------- batchnorm: per-column partial sums (deterministic) --------
__global__ void k_stats() {
    int col = threadIdx.x;
    int b = blockIdx.x;
    int r0 = b * 128;
    int r1 = r0 + 128;
    if (r1 > NN) r1 = NN;
    float s = 0.f, q = 0.f;
    for (int r = r0; r < r1; r++) {
        float v = g_out[(size_t)r * HID + col];
        s += v;
        q += v * v;
    }
    g_psum[b * HID + col] = s;
    g_psq [b * HID + col] = q;
}

__global__ void k_finalize(const float* __restrict__ gamma, const float* __restrict__ beta) {
    int col = threadIdx.x;
    float s = 0.f, q = 0.f;
    for (int b = 0; b < NROWB; b++) {
        s += g_psum[b * HID + col];
        q += g_psq [b * HID + col];
    }
    float mean = s / (float)NN;
    float var = q / (float)NN - mean * mean;   // biased var, matches jnp.var
    float sc = gamma[col] * rsqrtf(var + EPSV);
    g_scale[col] = sc;
    g_shift[col] = beta[col] - mean * sc;
}

// h += relu(out * scale + shift)
__global__ void k_update() {
    int i = blockIdx.x * blockDim.x + threadIdx.x;
    if (i >= NN * HID / 4) return;
    int c4 = (i & 63) << 2;
    float4 o = ((const float4*)g_out)[i];
    float4 h = ((float4*)g_h)[i];
    float v;
    v = o.x * g_scale[c4 + 0] + g_shift[c4 + 0]; h.x += fmaxf(v, 0.f);
    v = o.y * g_scale[c4 + 1] + g_shift[c4 + 1]; h.y += fmaxf(v, 0.f);
    v = o.z * g_scale[c4 + 2] + g_shift[c4 + 2]; h.z += fmaxf(v, 0.f);
    v = o.w * g_scale[c4 + 3] + g_shift[c4 + 3]; h.w += fmaxf(v, 0.f);
    ((float4*)g_h)[i] = h;
}

// ---------------- final: sigmoid(z2 . W3 + b3), warp per edge ----------------
__global__ void k_final(const float* __restrict__ W3, const float* __restrict__ b3,
                        float* __restrict__ out) {
    __shared__ float w[HID];
    if (threadIdx.x < HID) w[threadIdx.x] = W3[threadIdx.x];
    __syncthreads();
    int warp = threadIdx.x >> 5, lane = threadIdx.x & 31;
    int e = blockIdx.x * 8 + warp;
    if (e >= NE) return;
    const float4* z = (const float4*)(g_z2 + (size_t)e * HID);
    const float4* wv = (const float4*)w;
    float4 v0 = z[lane],  v1 = z[lane + 32];
    float4 w0 = wv[lane], w1 = wv[lane + 32];
    float acc = v0.x * w0.x + v0.y * w0.y + v0.z * w0.z + v0.w * w0.w
              + v1.x * w1.x + v1.y * w1.y + v1.z * w1.z + v1.w * w1.w;
#pragma unroll
    for (int off = 16; off > 0; off >>= 1)
        acc += __shfl_down_sync(0xffffffffu, acc, off);
    if (lane == 0) out[e] = 1.f / (1.f + expf(-(acc + b3[0])));
}

// ---------------- launch ----------------
extern "C" void kernel_launch(void* const* d_in, const int* in_sizes, int n_in,
                              void* d_out, int out_size) {
    const float* x     = (const float*)d_in[0];
    const int*   ei    = (const int*)  d_in[1];
    const float* Win   = (const float*)d_in[2];
    const float* Wrel  = (const float*)d_in[3];
    const float* brel  = (const float*)d_in[4];
    const float* Wroot = (const float*)d_in[5];
    const float* gamma = (const float*)d_in[6];
    const float* beta  = (const float*)d_in[7];
    const float* W1    = (const float*)d_in[8];
    const float* b1    = (const float*)d_in[9];
    const float* W2    = (const float*)d_in[10];
    const float* b2    = (const float*)d_in[11];
    const float* W3    = (const float*)d_in[12];
    const float* b3    = (const float*)d_in[13];
    float* out = (float*)d_out;
    const int* src = ei;
    const int* dst = ei + NE;

    // CSR build (replayed in-graph; deterministic after per-bucket sort)
    k_zero_hist<<<(NN + 255) / 256, 256>>>();
    k_hist<<<(NE + 255) / 256, 256>>>(dst);
    k_scan<<<1, 1024>>>();
    k_scatter<<<(NE + 255) / 256, 256>>>(dst);
    k_sortbuckets<<<(NN + 255) / 256, 256>>>(src);

    k_infc<<<2048, 256>>>(x, Win);

    for (int l = 0; l < NLAYERS; l++) {
        k_spmm<<<(NN + 7) / 8, 256>>>();
        k_gemm<512, 0, false><<<dim3(2, NROWB), 256>>>(
            Wrel + (size_t)l * HID * HID, Wroot + (size_t)l * HID * HID,
            brel + l * HID, nullptr, nullptr);
        k_stats<<<NROWB, 256>>>();
        k_finalize<<<1, 256>>>(gamma + l * HID, beta + l * HID);
        k_update<<<(NN * HID / 4 + 255) / 256, 256>>>();
    }

    // edge MLP
    k_gemm<512, 1, true><<<dim3(2, (NE + 127) / 128), 256>>>(W1, nullptr, b1, src, dst);
    k_gemm<256, 2, true><<<dim3(2, (NE + 127) / 128), 256>>>(W2, nullptr, b2, nullptr, nullptr);
    k_final<<<(NE + 7) / 8, 256>>>(W3, b3, out);
}

// round 7
// speedup vs baseline: 1.2957x; 1.2957x over previous
#include <cuda_runtime.h>
#include <math.h>

#define NN 50000
#define NE 500000
#define HID 256
#define NLAYERS 15
#define EPSV 1e-5f
#define NROWB ((NN + 127) / 128)   // 391 row blocks over nodes

// ---------------- device scratch (no allocations allowed) ----------------
__device__ float g_h  [(size_t)NN * HID];
__device__ float g_agg[(size_t)NN * HID];
__device__ float g_out[(size_t)NN * HID];
__device__ float g_uv [(size_t)2 * NN * HID];   // u = h@W1a.T | v = h@W1b.T
__device__ float g_part[(size_t)2 * NE];        // partial dots from edge GEMM
__device__ int   g_rowptr[NN + 1];
__device__ int   g_woff[NN];
__device__ int   g_hist[NN];
__device__ int   g_colidx[NE];
__device__ float g_psum[NROWB * HID];
__device__ float g_psq [NROWB * HID];
__device__ float g_scale[HID];
__device__ float g_shift[HID];

// ---------------- CSR build (deterministic) ----------------
__global__ void k_zero_hist() {
    int i = blockIdx.x * blockDim.x + threadIdx.x;
    if (i < NN) g_hist[i] = 0;
}

__global__ void k_hist(const int* __restrict__ dst) {
    int e = blockIdx.x * blockDim.x + threadIdx.x;
    if (e < NE) atomicAdd(&g_hist[dst[e]], 1);
}

__global__ void k_scan() {
    __shared__ int ss[1024];
    int t = threadIdx.x;
    int s0 = t * 49;
    int s1 = s0 + 49;
    if (s0 > NN) s0 = NN;
    if (s1 > NN) s1 = NN;
    int s = 0;
    for (int i = s0; i < s1; i++) s += g_hist[i];
    ss[t] = s;
    __syncthreads();
    for (int off = 1; off < 1024; off <<= 1) {
        int v = (t >= off) ? ss[t - off] : 0;
        __syncthreads();
        ss[t] += v;
        __syncthreads();
    }
    int run = (t > 0) ? ss[t - 1] : 0;
    for (int i = s0; i < s1; i++) {
        g_rowptr[i] = run;
        g_woff[i]   = run;
        run += g_hist[i];
    }
    if (t == 1023) g_rowptr[NN] = ss[1023];
}

__global__ void k_scatter(const int* __restrict__ dst) {
    int e = blockIdx.x * blockDim.x + threadIdx.x;
    if (e < NE) {
        int p = atomicAdd(&g_woff[dst[e]], 1);
        g_colidx[p] = e;   // edge id; sorted per bucket below -> deterministic
    }
}

__global__ void k_sortbuckets(const int* __restrict__ src) {
    int n = blockIdx.x * blockDim.x + threadIdx.x;
    if (n >= NN) return;
    int s = g_rowptr[n], t = g_rowptr[n + 1];
    for (int i = s + 1; i < t; i++) {
        int v = g_colidx[i];
        int j = i - 1;
        while (j >= s && g_colidx[j] > v) { g_colidx[j + 1] = g_colidx[j]; j--; }
        g_colidx[j + 1] = v;
    }
    for (int i = s; i < t; i++) g_colidx[i] = src[g_colidx[i]];
}

// ---------------- input FC: h = x @ W_in.T  (IN_CH = 2) ----------------
__global__ void k_infc(const float* __restrict__ x, const float* __restrict__ Win) {
    __shared__ float w0[HID], w1[HID];
    int j = threadIdx.x;
    w0[j] = Win[2 * j];
    w1[j] = Win[2 * j + 1];
    __syncthreads();
    for (int i = blockIdx.x; i < NN; i += gridDim.x) {
        float a = x[2 * i], b = x[2 * i + 1];
        g_h[(size_t)i * HID + j] = a * w0[j] + b * w1[j];
    }
}

// ---------------- SpMM: agg[n] = sum over in-edges of h[src] ----------------
__global__ void k_spmm() {
    int warp = threadIdx.x >> 5, lane = threadIdx.x & 31;
    int n = blockIdx.x * 8 + warp;
    if (n >= NN) return;
    int s = g_rowptr[n], e = g_rowptr[n + 1];
    float4 a0 = make_float4(0.f, 0.f, 0.f, 0.f);
    float4 a1 = make_float4(0.f, 0.f, 0.f, 0.f);
    for (int i = s; i < e; i++) {
        int sr = g_colidx[i];
        const float4* p = (const float4*)(g_h + (size_t)sr * HID);
        float4 v0 = p[lane];
        float4 v1 = p[lane + 32];
        a0.x += v0.x; a0.y += v0.y; a0.z += v0.z; a0.w += v0.w;
        a1.x += v1.x; a1.y += v1.y; a1.z += v1.z; a1.w += v1.w;
    }
    float4* q = (float4*)(g_agg + (size_t)n * HID);
    q[lane]      = a0;
    q[lane + 32] = a1;
}

// ---------------- tiled fp32 GEMM, 128x128x8, 256 threads, 8x8 microtile ----
// MODE 0: C=g_out, A=[g_agg|g_h] (K=512), B=[B0(Wrel)|B1(Wroot)], +bias
// MODE 1: C=g_uv+VSEL*NN*HID, A=g_h (K=256), B=B0 (W1 pre-offset, ldb=512)
// MODE 2: A[e,k]=relu(u[src]+v[dst]+b1[k]) on the fly (K=256), B=W2 (256x256);
//         epilogue: partial dot of relu(acc+b2) with w3 -> g_part[blockIdx.x*NE+e]
template <int MODE, int VSEL>
__global__ void __launch_bounds__(256, 2) k_gemm(
    const float* __restrict__ B0, const float* __restrict__ B1,
    const float* __restrict__ bias,   // MODE0: brel; MODE2: b2
    const float* __restrict__ w3,     // MODE2
    const float* __restrict__ b1e,    // MODE2
    const int* __restrict__ esrc, const int* __restrict__ edst)
{
    constexpr int M = (MODE == 2) ? NE : NN;
    constexpr int KTOT = (MODE == 0) ? 512 : 256;
    __shared__ float As[8][128];
    __shared__ float Bs[8][128];
    __shared__ int s_src[128];
    __shared__ int s_dst[128];

    const int tid = threadIdx.x;
    const int m0 = blockIdx.y * 128, n0 = blockIdx.x * 128;

    if (MODE == 2) {
        if (tid < 128) {
            int m = m0 + tid;
            s_src[tid] = (m < M) ? esrc[m] : 0;
        } else {
            int m = m0 + tid - 128;
            s_dst[tid - 128] = (m < M) ? edst[m] : 0;
        }
        __syncthreads();
    }

    const int tx = tid & 15, ty = tid >> 4;
    float acc[8][8];
#pragma unroll
    for (int i = 0; i < 8; i++)
#pragma unroll
        for (int j = 0; j < 8; j++) acc[i][j] = 0.f;

    const int arow = tid >> 1;
    const int a4 = (tid & 1) << 2;

    for (int k0 = 0; k0 < KTOT; k0 += 8) {
        float4 av = make_float4(0.f, 0.f, 0.f, 0.f);
        {
            int m = m0 + arow;
            int ka = k0 + a4;
            if (m < M) {
                if (MODE == 0) {
                    const float* ap = ((ka < 256) ? g_agg : g_h)
                                      + (size_t)m * HID + (ka & 255);
                    av = *(const float4*)ap;
                } else if (MODE == 1) {
                    av = *(const float4*)(g_h + (size_t)m * HID + ka);
                } else {
                    float4 uu = *(const float4*)(g_uv + (size_t)s_src[arow] * HID + ka);
                    float4 vv = *(const float4*)(g_uv + ((size_t)NN + s_dst[arow]) * HID + ka);
                    float4 bb = *(const float4*)(b1e + ka);
                    av.x = fmaxf(uu.x + vv.x + bb.x, 0.f);
                    av.y = fmaxf(uu.y + vv.y + bb.y, 0.f);
                    av.z = fmaxf(uu.z + vv.z + bb.z, 0.f);
                    av.w = fmaxf(uu.w + vv.w + bb.w, 0.f);
                }
            }
        }
        float4 bv;
        {
            int nn = n0 + arow;
            int kb = k0 + a4;
            const float* bp;
            if (MODE == 0)      bp = ((kb < 256) ? B0 : B1) + nn * 256 + (kb & 255);
            else if (MODE == 1) bp = B0 + nn * 512 + kb;
            else                bp = B0 + nn * 256 + kb;
            bv = *(const float4*)bp;
        }
        __syncthreads();
        As[a4 + 0][arow] = av.x; As[a4 + 1][arow] = av.y;
        As[a4 + 2][arow] = av.z; As[a4 + 3][arow] = av.w;
        Bs[a4 + 0][arow] = bv.x; Bs[a4 + 1][arow] = bv.y;
        Bs[a4 + 2][arow] = bv.z; Bs[a4 + 3][arow] = bv.w;
        __syncthreads();
#pragma unroll
        for (int kk = 0; kk < 8; kk++) {
            float4 aa0 = *(const float4*)&As[kk][ty * 8];
            float4 aa1 = *(const float4*)&As[kk][ty * 8 + 4];
            float4 bb0 = *(const float4*)&Bs[kk][tx * 8];
            float4 bb1 = *(const float4*)&Bs[kk][tx * 8 + 4];
            float a[8] = {aa0.x, aa0.y, aa0.z, aa0.w, aa1.x, aa1.y, aa1.z, aa1.w};
            float b[8] = {bb0.x, bb0.y, bb0.z, bb0.w, bb1.x, bb1.y, bb1.z, bb1.w};
#pragma unroll
            for (int i = 0; i < 8; i++)
#pragma unroll
                for (int j = 0; j < 8; j++) acc[i][j] += a[i] * b[j];
        }
    }

    if (MODE == 2) {
        // per-row partial dot over this block's 128 cols:
        // s[i] = sum_j relu(acc[i][j] + b2[col]) * w3[col]
        float bcol[8], wcol[8];
#pragma unroll
        for (int j = 0; j < 8; j++) {
            int n = n0 + tx * 8 + j;
            bcol[j] = bias[n];
            wcol[j] = w3[n];
        }
#pragma unroll
        for (int i = 0; i < 8; i++) {
            float s = 0.f;
#pragma unroll
            for (int j = 0; j < 8; j++)
                s += fmaxf(acc[i][j] + bcol[j], 0.f) * wcol[j];
            // reduce over tx (lane bits 0..3); ty bit is lane bit 4, untouched
            s += __shfl_xor_sync(0xffffffffu, s, 1);
            s += __shfl_xor_sync(0xffffffffu, s, 2);
            s += __shfl_xor_sync(0xffffffffu, s, 4);
            s += __shfl_xor_sync(0xffffffffu, s, 8);
            if (tx == 0) {
                int m = m0 + ty * 8 + i;
                if (m < M) g_part[(size_t)blockIdx.x * NE + m] = s;
            }
        }
    } else {
        float* crow = (MODE == 0) ? g_out : (g_uv + (size_t)VSEL * NN * HID);
#pragma unroll
        for (int i = 0; i < 8; i++) {
            int m = m0 + ty * 8 + i;
            if (m < M) {
#pragma unroll
                for (int j = 0; j < 8; j += 4) {
                    int n = n0 + tx * 8 + j;
                    float4 v;
                    if (MODE == 0) {
                        v.x = acc[i][j + 0] + bias[n + 0];
                        v.y = acc[i][j + 1] + bias[n + 1];
                        v.z = acc[i][j + 2] + bias[n + 2];
                        v.w = acc[i][j + 3] + bias[n + 3];
                    } else {
                        v.x = acc[i][j + 0]; v.y = acc[i][j + 1];
                        v.z = acc[i][j + 2]; v.w = acc[i][j + 3];
                    }
                    *(float4*)(crow + (size_t)m * HID + n) = v;
                }
            }
        }
    }
}

// ---------------- batchnorm: per-column partial sums (deterministic) --------
__global__ void k_stats() {
    int col = threadIdx.x;
    int b = blockIdx.x;
    int r0 = b * 128;
    int r1 = r0 + 128;
    if (r1 > NN) r1 = NN;
    float s = 0.f, q = 0.f;
    for (int r = r0; r < r1; r++) {
        float v = g_out[(size_t)r * HID + col];
        s += v;
        q += v * v;
    }
    g_psum[b * HID + col] = s;
    g_psq [b * HID + col] = q;
}

__global__ void k_finalize(const float* __restrict__ gamma, const float* __restrict__ beta) {
    int col = threadIdx.x;
    float s = 0.f, q = 0.f;
    for (int b = 0; b < NROWB; b++) {
        s += g_psum[b * HID + col];
        q += g_psq [b * HID + col];
    }
    float mean = s / (float)NN;
    float var = q / (float)NN - mean * mean;   // biased var, matches jnp.var
    float sc = gamma[col] * rsqrtf(var + EPSV);
    g_scale[col] = sc;
    g_shift[col] = beta[col] - mean * sc;
}

// h += relu(out * scale + shift)
__global__ void k_update() {
    int i = blockIdx.x * blockDim.x + threadIdx.x;
    if (i >= NN * HID / 4) return;
    int c4 = (i & 63) << 2;
    float4 o = ((const float4*)g_out)[i];
    float4 h = ((float4*)g_h)[i];
    float v;
    v = o.x * g_scale[c4 + 0] + g_shift[c4 + 0]; h.x += fmaxf(v, 0.f);
    v = o.y * g_scale[c4 + 1] + g_shift[c4 + 1]; h.y += fmaxf(v, 0.f);
    v = o.z * g_scale[c4 + 2] + g_shift[c4 + 2]; h.z += fmaxf(v, 0.f);
    v = o.w * g_scale[c4 + 3] + g_shift[c4 + 3]; h.w += fmaxf(v, 0.f);
    ((float4*)g_h)[i] = h;
}

// ---------------- combine partial dots -> sigmoid ----------------
__global__ void k_sig(const float* __restrict__ b3, float* __restrict__ out) {
    int e = blockIdx.x * blockDim.x + threadIdx.x;
    if (e < NE)
        out[e] = 1.f / (1.f + expf(-(g_part[e] + g_part[NE + e] + b3[0])));
}

// ---------------- launch ----------------
extern "C" void kernel_launch(void* const* d_in, const int* in_sizes, int n_in,
                              void* d_out, int out_size) {
    const float* x     = (const float*)d_in[0];
    const int*   ei    = (const int*)  d_in[1];
    const float* Win   = (const float*)d_in[2];
    const float* Wrel  = (const float*)d_in[3];
    const float* brel  = (const float*)d_in[4];
    const float* Wroot = (const float*)d_in[5];
    const float* gamma = (const float*)d_in[6];
    const float* beta  = (const float*)d_in[7];
    const float* W1    = (const float*)d_in[8];
    const float* b1    = (const float*)d_in[9];
    const float* W2    = (const float*)d_in[10];
    const float* b2    = (const float*)d_in[11];
    const float* W3    = (const float*)d_in[12];
    const float* b3    = (const float*)d_in[13];
    float* out = (float*)d_out;
    const int* src = ei;
    const int* dst = ei + NE;

    // CSR build (replayed in-graph; deterministic after per-bucket sort)
    k_zero_hist<<<(NN + 255) / 256, 256>>>();
    k_hist<<<(NE + 255) / 256, 256>>>(dst);
    k_scan<<<1, 1024>>>();
    k_scatter<<<(NE + 255) / 256, 256>>>(dst);
    k_sortbuckets<<<(NN + 255) / 256, 256>>>(src);

    k_infc<<<2048, 256>>>(x, Win);

    for (int l = 0; l < NLAYERS; l++) {
        k_spmm<<<(NN + 7) / 8, 256>>>();
        k_gemm<0, 0><<<dim3(2, NROWB), 256>>>(
            Wrel + (size_t)l * HID * HID, Wroot + (size_t)l * HID * HID,
            brel + l * HID, nullptr, nullptr, nullptr, nullptr);
        k_stats<<<NROWB, 256>>>();
        k_finalize<<<1, 256>>>(gamma + l * HID, beta + l * HID);
        k_update<<<(NN * HID / 4 + 255) / 256, 256>>>();
    }

    // edge MLP, decomposed: u = h@W1a.T, v = h@W1b.T (per-node, 10x fewer FLOPs)
    k_gemm<1, 0><<<dim3(2, NROWB), 256>>>(W1,       nullptr, nullptr,
                                          nullptr, nullptr, nullptr, nullptr);
    k_gemm<1, 1><<<dim3(2, NROWB), 256>>>(W1 + 256, nullptr, nullptr,
                                          nullptr, nullptr, nullptr, nullptr);
    // fused: z1 = relu(u[src]+v[dst]+b1) built in A-load; z2 = z1@W2.T;
    // epilogue computes partial relu(z2+b2)·w3 per 128-col block
    k_gemm<2, 0><<<dim3(2, (NE + 127) / 128), 256>>>(W2, nullptr, b2,
                                                     W3, b1, src, dst);
    k_sig<<<(NE + 255) / 256, 256>>>(b3, out);
}